// round 8
// baseline (speedup 1.0000x reference)
#include <cuda_runtime.h>

// ---------------------------------------------------------------------------
// PlainRNN: h_t = tanh(h_{t-1} @ W_eff + b_eff) with
//   W_eff = W_h2h + W_h2o @ W_i2h  (x feedback folded into the recurrence)
// 511 step-kernel launches (graph-captured). out[t] = h_t @ W_h2o + b_h2o
// is one big batched GEMM at the end.
//
// GEMM core: 32x64 CTA tile, BK=32, 256 threads.
// Warp = 8 rows x 32 cols sub-tile (thread = 2x4) -> per warp-kk only
// 4 broadcast A-words + 8 contiguous B-words on the smem crossbar;
// inner loop is FFMA2 (fma.rn.f32x2) issue-bound.
// ---------------------------------------------------------------------------

#define INPUT   128
#define HIDDEN  1024
#define OUTPUT  128
#define BATCH   256
#define TSTEPS  512

__device__ float g_H[TSTEPS][BATCH][HIDDEN];   // h_t for t=1..511
__device__ float g_Weff[HIDDEN * HIDDEN];
__device__ float g_beff[HIDDEN];
__device__ float g_b1[HIDDEN];

// ---------------- packed fp32x2 helpers ------------------------------------
__device__ __forceinline__ unsigned long long pack2(float lo, float hi) {
    unsigned long long r;
    asm("mov.b64 %0, {%1, %2};" : "=l"(r) : "f"(lo), "f"(hi));
    return r;
}
__device__ __forceinline__ void unpack2(unsigned long long v, float& lo, float& hi) {
    asm("mov.b64 {%0, %1}, %2;" : "=f"(lo), "=f"(hi) : "l"(v));
}
__device__ __forceinline__ void ffma2(unsigned long long& d,
                                      unsigned long long a,
                                      unsigned long long b) {
    asm("fma.rn.f32x2 %0, %1, %2, %0;" : "+l"(d) : "l"(a), "l"(b));
}

// ---------------------------------------------------------------------------
// One 32x64 output tile of C = act(A[.,K] @ B[K,.] + bias), BK=32,
// double-buffered smem, 256 threads. K % 32 == 0.
// ---------------------------------------------------------------------------
template <bool TANH>
__device__ __forceinline__ void gemm_tile(
    const float* __restrict__ A, int lda,
    const float* __restrict__ B, int ldb,
    const float* __restrict__ bias,
    float* __restrict__ C, int ldc,
    int K, int rowBase, int colBase)
{
    // Asd[k][m] = (A[m], A[m]) packed pair; row stride 34*8=272 (16B-aligned)
    __shared__ unsigned long long Asd[2][32][34];
    __shared__ float Bs[2][32][68];

    const int tid = threadIdx.x;
    const int w = tid >> 5, l = tid & 31;
    const int tr = ((w >> 1) << 3) + ((l >> 3) << 1);   // thread rows tr, tr+1
    const int tc = ((w & 1) << 5) + ((l & 7) << 2);     // thread cols tc..tc+3

    // stagers
    const int am = tid >> 3;            // 0..31 (row)
    const int ak = (tid & 7) << 2;      // 0,4,...,28 (k)
    const int bk = tid >> 4;            // 0..15 (k row, +16 for second)
    const int bn = (tid & 15) << 2;     // 0..60 (col)

    const float* Ap = A + (size_t)(rowBase + am) * lda + ak;
    const float* Bp = B + (size_t)bk * ldb + colBase + bn;

    unsigned long long acc[2][2];
    acc[0][0] = acc[0][1] = acc[1][0] = acc[1][1] = 0ull;

    float4 rA  = *(const float4*)Ap;
    float4 rB0 = *(const float4*)Bp;
    float4 rB1 = *(const float4*)(Bp + (size_t)16 * ldb);

    const int nT = K >> 5;
    for (int t = 0; t < nT; ++t) {
        const int buf = t & 1;
        Asd[buf][ak + 0][am] = pack2(rA.x, rA.x);
        Asd[buf][ak + 1][am] = pack2(rA.y, rA.y);
        Asd[buf][ak + 2][am] = pack2(rA.z, rA.z);
        Asd[buf][ak + 3][am] = pack2(rA.w, rA.w);
        *(float4*)&Bs[buf][bk][bn]      = rB0;
        *(float4*)&Bs[buf][bk + 16][bn] = rB1;
        __syncthreads();
        if (t + 1 < nT) {
            rA  = *(const float4*)(Ap + (t + 1) * 32);
            rB0 = *(const float4*)(Bp + (size_t)(t + 1) * 32 * ldb);
            rB1 = *(const float4*)(Bp + (size_t)((t + 1) * 32 + 16) * ldb);
        }
#pragma unroll
        for (int kk = 0; kk < 32; ++kk) {
            ulonglong2 ap = *(const ulonglong2*)&Asd[buf][kk][tr];
            ulonglong2 bp = *(const ulonglong2*)&Bs[buf][kk][tc];
            ffma2(acc[0][0], ap.x, bp.x);
            ffma2(acc[0][1], ap.x, bp.y);
            ffma2(acc[1][0], ap.y, bp.x);
            ffma2(acc[1][1], ap.y, bp.y);
        }
        // single sync per tile: writes(t+1) target buf^1 and happen after
        // sync(t); all reads of buf^1 (compute(t-1)) precede sync(t).
    }

    float4 bv = *(const float4*)&bias[colBase + tc];
    float o[2][4];
#pragma unroll
    for (int r = 0; r < 2; ++r) {
        unpack2(acc[r][0], o[r][0], o[r][1]);
        unpack2(acc[r][1], o[r][2], o[r][3]);
        o[r][0] += bv.x; o[r][1] += bv.y; o[r][2] += bv.z; o[r][3] += bv.w;
        if (TANH) {
#pragma unroll
            for (int c = 0; c < 4; ++c) o[r][c] = tanhf(o[r][c]);
        }
        float* cp = &C[(size_t)(rowBase + tr + r) * ldc + colBase + tc];
        *(float4*)cp = make_float4(o[r][0], o[r][1], o[r][2], o[r][3]);
    }
}

// ---------------------------- wrappers -------------------------------------

// h_1 = tanh(x_0 @ W_i2h + b_i2h + b_h2h)           grid (16, 8)
__global__ void __launch_bounds__(256, 1)
rnn_first(const float* __restrict__ x0, const float* __restrict__ Wi2h) {
    gemm_tile<true>(x0, INPUT, Wi2h, HIDDEN, g_b1,
                    &g_H[1][0][0], HIDDEN, INPUT,
                    blockIdx.y * 32, blockIdx.x * 64);
}

// h_t = tanh(h_{t-1} @ W_eff + b_eff)               grid (16, 8)
__global__ void __launch_bounds__(256, 1)
rnn_step(int t) {
    gemm_tile<true>(&g_H[t - 1][0][0], HIDDEN, g_Weff, HIDDEN, g_beff,
                    &g_H[t][0][0], HIDDEN, HIDDEN,
                    blockIdx.y * 32, blockIdx.x * 64);
}

// out[t] = h_t @ W_h2o + b_h2o for t=1..511         grid (2, 4088)
__global__ void __launch_bounds__(256, 1)
out_proj(const float* __restrict__ Wh2o, const float* __restrict__ bh2o,
         float* __restrict__ out) {
    gemm_tile<false>(&g_H[1][0][0], HIDDEN, Wh2o, OUTPUT, bh2o,
                     out + BATCH * OUTPUT, OUTPUT, HIDDEN,
                     blockIdx.y * 32, blockIdx.x * 64);
}

// ---------------------------- prep kernels ---------------------------------
__global__ void prep_weff(const float* __restrict__ Wh2h,
                          const float* __restrict__ Wh2o,
                          const float* __restrict__ Wi2h) {
    int idx = blockIdx.x * blockDim.x + threadIdx.x;
    int k = idx >> 10;
    int j = idx & 1023;
    float s = Wh2h[idx];
    const float* wo = &Wh2o[k * OUTPUT];
#pragma unroll 8
    for (int i = 0; i < OUTPUT; ++i)
        s += wo[i] * Wi2h[i * HIDDEN + j];
    g_Weff[idx] = s;
}

__global__ void prep_bias(const float* __restrict__ bi2h,
                          const float* __restrict__ bh2h,
                          const float* __restrict__ bh2o,
                          const float* __restrict__ Wi2h) {
    int j = blockIdx.x * blockDim.x + threadIdx.x;
    if (j >= HIDDEN) return;
    float base = bi2h[j] + bh2h[j];
    g_b1[j] = base;
    float s = base;
#pragma unroll 8
    for (int i = 0; i < OUTPUT; ++i)
        s += bh2o[i] * Wi2h[i * HIDDEN + j];
    g_beff[j] = s;
}

__global__ void copy_x0(const float* __restrict__ x0, float* __restrict__ out) {
    int i = blockIdx.x * blockDim.x + threadIdx.x;
    if (i < BATCH * OUTPUT) out[i] = x0[i];
}

// ---------------------------- launcher -------------------------------------
extern "C" void kernel_launch(void* const* d_in, const int* in_sizes, int n_in,
                              void* d_out, int out_size) {
    const float* x0   = (const float*)d_in[0];
    const float* Wi2h = (const float*)d_in[1];
    const float* bi2h = (const float*)d_in[2];
    const float* Wh2h = (const float*)d_in[3];
    const float* bh2h = (const float*)d_in[4];
    const float* Wh2o = (const float*)d_in[5];
    const float* bh2o = (const float*)d_in[6];
    float* out = (float*)d_out;

    prep_weff<<<(HIDDEN * HIDDEN) / 256, 256>>>(Wh2h, Wh2o, Wi2h);
    prep_bias<<<(HIDDEN + 255) / 256, 256>>>(bi2h, bh2h, bh2o, Wi2h);
    copy_x0<<<(BATCH * OUTPUT + 255) / 256, 256>>>(x0, out);

    const dim3 stepGrid(HIDDEN / 64, BATCH / 32);   // (16, 8) = 128 CTAs
    rnn_first<<<stepGrid, 256>>>(x0, Wi2h);
    for (int t = 2; t < TSTEPS; ++t)
        rnn_step<<<stepGrid, 256>>>(t);

    out_proj<<<dim3(OUTPUT / 64, ((TSTEPS - 1) * BATCH) / 32), 256>>>(Wh2o, bh2o, out);
}